// round 17
// baseline (speedup 1.0000x reference)
#include <cuda_runtime.h>
#include <cstdint>
#include <math.h>

// x [128, 1, 512, 512] fp32.
//   pred = softplus(x); m = max over sample; out = (m > 1e-8) ? pred/m : pred.
// softplus monotone => m = softplus(max(x)).
//
// R17 = R16 (PDL-chained bulk two-kernel, best 55.7us) with 8 slices of 16
// samples (16.8 MB). Rationale: at 55.7us we sit at the ~7.2 TB/s LTS /
// mixed-DRAM ceiling for the fixed 402 MB of L2 traffic; the only remaining
// recoverable waste is (a) residual K2 re-read DRAM misses at coarse slice
// granularity and (b) per-launch tail quantization. Finer slices fix (a)
// (huge L2 residency margin) and tighten (b) (PDL overlap at finer grain).
// Kernel bodies identical to R16 (proven 32-reg forms).

#define SAMPLES 128
#define SLICES 8
#define SAMPLES_PER_SLICE (SAMPLES / SLICES)       // 16
#define SAMPLE_ELEMS (512 * 512)                   // 262144
#define SAMPLE_N4 (SAMPLE_ELEMS / 4)               // 65536 float4
#define CHUNKS 32                                  // CTAs per sample
#define CHUNK_N4 (SAMPLE_N4 / CHUNKS)              // 2048 float4 per CTA
#define SLICE_BLOCKS (SAMPLES_PER_SLICE * CHUNKS)  // 512
#define THREADS 256                                // 8 float4 per thread
#define EPS 1e-8f
#define LOG2E 1.4426950408889634f
#define LN2   0.6931471805599453f

__device__ float g_partial[SAMPLES * CHUNKS];      // disjoint slots per slice

__device__ __forceinline__ float softplus_accurate(float x) {
    return fmaxf(x, 0.0f) + log1pf(__expf(-fabsf(x)));
}
__device__ __forceinline__ float ex2f(float x) {
    float r; asm("ex2.approx.ftz.f32 %0, %1;" : "=f"(r) : "f"(x)); return r;
}
__device__ __forceinline__ float lg2f(float x) {
    float r; asm("lg2.approx.ftz.f32 %0, %1;" : "=f"(r) : "f"(x)); return r;
}
__device__ __forceinline__ float softplus_scaled(float x, float scale, float scale_ln2) {
    float t = ex2f(-LOG2E * fabsf(x));             // e^(-|x|)
    float l = lg2f(1.0f + t);                      // log2(1 + e^-|x|)
    return fmaf(scale, fmaxf(x, 0.0f), scale_ln2 * l);
}

// ---------- K1: per-chunk max over one slice (no PDL wait needed) ----------
__global__ __launch_bounds__(THREADS)
void max_kernel(const float* __restrict__ x_slice, float* __restrict__ partial_slice) {
    asm volatile("griddepcontrol.launch_dependents;");

    const float4* __restrict__ xin =
        reinterpret_cast<const float4*>(x_slice) + (size_t)blockIdx.x * CHUNK_N4;
    const int tid = threadIdx.x;

    float m0 = -INFINITY, m1 = -INFINITY, m2 = -INFINITY, m3 = -INFINITY;
    #pragma unroll
    for (int it = 0; it < 2; it++) {
        int base = it * 4 * THREADS + tid;
        float4 a = xin[base];
        float4 b = xin[base + THREADS];
        float4 c = xin[base + 2 * THREADS];
        float4 d = xin[base + 3 * THREADS];
        m0 = fmaxf(m0, fmaxf(fmaxf(a.x, a.y), fmaxf(a.z, a.w)));
        m1 = fmaxf(m1, fmaxf(fmaxf(b.x, b.y), fmaxf(b.z, b.w)));
        m2 = fmaxf(m2, fmaxf(fmaxf(c.x, c.y), fmaxf(c.z, c.w)));
        m3 = fmaxf(m3, fmaxf(fmaxf(d.x, d.y), fmaxf(d.z, d.w)));
    }
    float m = fmaxf(fmaxf(m0, m1), fmaxf(m2, m3));

    #pragma unroll
    for (int off = 16; off; off >>= 1)
        m = fmaxf(m, __shfl_xor_sync(0xFFFFFFFFu, m, off));

    __shared__ float red[THREADS / 32];
    if ((tid & 31) == 0) red[tid >> 5] = m;
    __syncthreads();
    if (tid < (THREADS / 32)) {
        float v = red[tid];
        #pragma unroll
        for (int off = (THREADS / 64); off; off >>= 1)
            v = fmaxf(v, __shfl_xor_sync(0xFFFFFFFFu, v, off));
        if (tid == 0) partial_slice[blockIdx.x] = v;   // distinct slot, no atomic
    }
}

// ---------- K2: loads first, PDL wait, then reduce partials + normalize ----------
__global__ __launch_bounds__(THREADS)
void norm_kernel(const float* __restrict__ x_slice, float* __restrict__ out_slice,
                 const float* __restrict__ partial_slice) {
    asm volatile("griddepcontrol.launch_dependents;");

    const int sample = blockIdx.x >> 5;              // / CHUNKS (within slice)
    const size_t off4 = (size_t)blockIdx.x * CHUNK_N4;
    const float4* __restrict__ xin = reinterpret_cast<const float4*>(x_slice) + off4;
    float4* __restrict__ o = reinterpret_cast<float4*>(out_slice) + off4;
    const int tid = threadIdx.x;

    // Issue first batch of loads BEFORE waiting on K1 (no dependency on it).
    float4 a0 = __ldcs(&xin[tid]);
    float4 b0 = __ldcs(&xin[tid + THREADS]);
    float4 c0 = __ldcs(&xin[tid + 2 * THREADS]);
    float4 d0 = __ldcs(&xin[tid + 3 * THREADS]);

    // Require the preceding max_kernel to be complete (partials visible).
    asm volatile("griddepcontrol.wait;" ::: "memory");

    __shared__ float s_scale;
    if (tid < 32) {
        float v = partial_slice[sample * CHUNKS + tid];  // CHUNKS == 32
        #pragma unroll
        for (int off = 16; off; off >>= 1)
            v = fmaxf(v, __shfl_xor_sync(0xFFFFFFFFu, v, off));
        if (tid == 0) {
            float sm = softplus_accurate(v);   // = max(softplus(x)), monotone
            s_scale = (sm > EPS) ? (1.0f / sm) : 1.0f;
        }
    }
    __syncthreads();
    const float scale = s_scale;
    const float scale_ln2 = scale * LN2;

    // Batch 1 (loads already in flight / done).
    {
        float4 ra, rb, rc, rd;
        ra.x = softplus_scaled(a0.x, scale, scale_ln2);
        ra.y = softplus_scaled(a0.y, scale, scale_ln2);
        ra.z = softplus_scaled(a0.z, scale, scale_ln2);
        ra.w = softplus_scaled(a0.w, scale, scale_ln2);
        rb.x = softplus_scaled(b0.x, scale, scale_ln2);
        rb.y = softplus_scaled(b0.y, scale, scale_ln2);
        rb.z = softplus_scaled(b0.z, scale, scale_ln2);
        rb.w = softplus_scaled(b0.w, scale, scale_ln2);
        rc.x = softplus_scaled(c0.x, scale, scale_ln2);
        rc.y = softplus_scaled(c0.y, scale, scale_ln2);
        rc.z = softplus_scaled(c0.z, scale, scale_ln2);
        rc.w = softplus_scaled(c0.w, scale, scale_ln2);
        rd.x = softplus_scaled(d0.x, scale, scale_ln2);
        rd.y = softplus_scaled(d0.y, scale, scale_ln2);
        rd.z = softplus_scaled(d0.z, scale, scale_ln2);
        rd.w = softplus_scaled(d0.w, scale, scale_ln2);
        __stcs(&o[tid], ra);
        __stcs(&o[tid + THREADS], rb);
        __stcs(&o[tid + 2 * THREADS], rc);
        __stcs(&o[tid + 3 * THREADS], rd);
    }
    // Batch 2.
    {
        int base = 4 * THREADS + tid;
        float4 a = __ldcs(&xin[base]);
        float4 b = __ldcs(&xin[base + THREADS]);
        float4 c = __ldcs(&xin[base + 2 * THREADS]);
        float4 d = __ldcs(&xin[base + 3 * THREADS]);
        float4 ra, rb, rc, rd;
        ra.x = softplus_scaled(a.x, scale, scale_ln2);
        ra.y = softplus_scaled(a.y, scale, scale_ln2);
        ra.z = softplus_scaled(a.z, scale, scale_ln2);
        ra.w = softplus_scaled(a.w, scale, scale_ln2);
        rb.x = softplus_scaled(b.x, scale, scale_ln2);
        rb.y = softplus_scaled(b.y, scale, scale_ln2);
        rb.z = softplus_scaled(b.z, scale, scale_ln2);
        rb.w = softplus_scaled(b.w, scale, scale_ln2);
        rc.x = softplus_scaled(c.x, scale, scale_ln2);
        rc.y = softplus_scaled(c.y, scale, scale_ln2);
        rc.z = softplus_scaled(c.z, scale, scale_ln2);
        rc.w = softplus_scaled(c.w, scale, scale_ln2);
        rd.x = softplus_scaled(d.x, scale, scale_ln2);
        rd.y = softplus_scaled(d.y, scale, scale_ln2);
        rd.z = softplus_scaled(d.z, scale, scale_ln2);
        rd.w = softplus_scaled(d.w, scale, scale_ln2);
        __stcs(&o[base], ra);
        __stcs(&o[base + THREADS], rb);
        __stcs(&o[base + 2 * THREADS], rc);
        __stcs(&o[base + 3 * THREADS], rd);
    }
}

extern "C" void kernel_launch(void* const* d_in, const int* in_sizes, int n_in,
                              void* d_out, int out_size) {
    const float* x = (const float*)d_in[0];
    float* out = (float*)d_out;

    float* gp = nullptr;
    cudaGetSymbolAddress((void**)&gp, g_partial);

    cudaLaunchAttribute attr[1];
    attr[0].id = cudaLaunchAttributeProgrammaticStreamSerialization;
    attr[0].val.programmaticStreamSerializationAllowed = 1;

    cudaLaunchConfig_t cfg = {};
    cfg.gridDim = dim3(SLICE_BLOCKS);
    cfg.blockDim = dim3(THREADS);
    cfg.dynamicSmemBytes = 0;
    cfg.stream = 0;                      // legacy default stream (captured)
    cfg.attrs = attr;
    cfg.numAttrs = 1;

    const size_t se = (size_t)SAMPLES_PER_SLICE * SAMPLE_ELEMS;
    for (int s = 0; s < SLICES; s++) {
        const float* xs = x + s * se;
        float* os = out + s * se;
        float* ps = gp + s * SLICE_BLOCKS;
        cudaLaunchKernelEx(&cfg, max_kernel, xs, ps);
        cudaLaunchKernelEx(&cfg, norm_kernel, xs, os, (const float*)ps);
    }
}